// round 10
// baseline (speedup 1.0000x reference)
#include <cuda_runtime.h>

// Problem constants (fixed by setup_inputs)
#define BB 8
#define SS 4096
#define NN 32
#define HH 32
#define DD 64
#define OO 32
#define ROWS (BB*SS)        // 32768
#define LN_EPS 1e-5f

// Scratch for neighbor aggregation (sum over N of h@nW2, WITHOUT nb2 bias;
// K2 adds N*nb2). 32768 rows x 32 floats = 4 MB.
__device__ float g_nagg[ROWS * HH];

// ---------------------------------------------------------------------------
// K1: neighbor branch.
// 4 threads per row, each handles 8 neighbors, partials combined via shfl.
// thread t: row = t>>2, quarter q = t&3 -> neighbors n in [q*8, q*8+8).
// ---------------------------------------------------------------------------
__global__ __launch_bounds__(256) void k1_neighbors(
    const float* __restrict__ neighbors,   // (B,N,S)
    const float* __restrict__ edge,        // (B,S,N)
    const float* __restrict__ nW1,         // (2,H) row-major
    const float* __restrict__ nb1,         // (H)
    const float* __restrict__ nlg,         // (H)
    const float* __restrict__ nlb,         // (H)
    const float* __restrict__ nW2)         // (H,H) row-major
{
    __shared__ float s_w1a[HH];            // nW1[0][j]
    __shared__ float s_w1b[HH];            // nW1[1][j]
    __shared__ float s_b1[HH];
    __shared__ float s_g[HH];
    __shared__ float s_lb[HH];
    __shared__ float s_w2[HH * HH];

    const int tid = threadIdx.x;
    if (tid < HH) {
        s_w1a[tid] = nW1[tid];
        s_w1b[tid] = nW1[HH + tid];
        s_b1[tid]  = nb1[tid];
        s_g[tid]   = nlg[tid];
        s_lb[tid]  = nlb[tid];
    }
    for (int i = tid; i < HH * HH; i += blockDim.x) s_w2[i] = nW2[i];
    __syncthreads();

    const int t   = blockIdx.x * blockDim.x + tid;
    const int row = t >> 2;
    const int q   = t & 3;
    const int b   = row >> 12;          // 4096 rows per batch
    const int s   = row & (SS - 1);

    const float4* Av  = (const float4*)s_w1a;
    const float4* Bv  = (const float4*)s_w1b;
    const float4* Cv  = (const float4*)s_b1;
    const float4* Gv  = (const float4*)s_g;
    const float4* Lv  = (const float4*)s_lb;
    const float4* W2v = (const float4*)s_w2;

    float acc[HH];
    #pragma unroll
    for (int k = 0; k < HH; k++) acc[k] = 0.0f;

    const float* nbase = neighbors + (size_t)b * (NN * SS) + s;
    const float* ebase = edge + (size_t)row * NN + q * 8;

    // Rolled over the 8 neighbors (keeps code footprint ~26KB, fits I$).
    #pragma unroll 1
    for (int i = 0; i < 8; i++) {
        const int n = q * 8 + i;
        const float v0 = nbase[(size_t)n * SS];   // neighbors[b][n][s] (coalesced)
        const float v1 = ebase[i];                // edge[b][s][n] (L1-resident after i=0)

        float h[HH];
        float sum = 0.0f;
        #pragma unroll
        for (int j4 = 0; j4 < 8; j4++) {
            float4 a  = Av[j4];
            float4 bb = Bv[j4];
            float4 c  = Cv[j4];
            float h0 = fmaf(v0, a.x, fmaf(v1, bb.x, c.x));
            float h1 = fmaf(v0, a.y, fmaf(v1, bb.y, c.y));
            float h2 = fmaf(v0, a.z, fmaf(v1, bb.z, c.z));
            float h3 = fmaf(v0, a.w, fmaf(v1, bb.w, c.w));
            h[j4*4+0] = h0; h[j4*4+1] = h1; h[j4*4+2] = h2; h[j4*4+3] = h3;
            sum += ((h0 + h1) + (h2 + h3));
        }
        const float m = sum * (1.0f / HH);
        float var = 0.0f;
        #pragma unroll
        for (int j = 0; j < HH; j++) {
            float d = h[j] - m;
            var = fmaf(d, d, var);
        }
        const float r = rsqrtf(var * (1.0f / HH) + LN_EPS);
        #pragma unroll
        for (int j4 = 0; j4 < 8; j4++) {
            float4 g4 = Gv[j4];
            float4 b4 = Lv[j4];
            h[j4*4+0] = fmaxf(fmaf((h[j4*4+0] - m) * r, g4.x, b4.x), 0.0f);
            h[j4*4+1] = fmaxf(fmaf((h[j4*4+1] - m) * r, g4.y, b4.y), 0.0f);
            h[j4*4+2] = fmaxf(fmaf((h[j4*4+2] - m) * r, g4.z, b4.z), 0.0f);
            h[j4*4+3] = fmaxf(fmaf((h[j4*4+3] - m) * r, g4.w, b4.w), 0.0f);
        }
        // acc += h @ nW2  (dominant cost: 1024 FMA per neighbor)
        #pragma unroll
        for (int j = 0; j < HH; j++) {
            const float hv = h[j];
            #pragma unroll
            for (int k4 = 0; k4 < 8; k4++) {
                float4 w = W2v[j * 8 + k4];
                acc[k4*4+0] = fmaf(hv, w.x, acc[k4*4+0]);
                acc[k4*4+1] = fmaf(hv, w.y, acc[k4*4+1]);
                acc[k4*4+2] = fmaf(hv, w.z, acc[k4*4+2]);
                acc[k4*4+3] = fmaf(hv, w.w, acc[k4*4+3]);
            }
        }
    }

    // Combine 4 partials (lanes 4r..4r+3 share a row).
    #pragma unroll
    for (int k = 0; k < HH; k++) acc[k] += __shfl_xor_sync(0xffffffffu, acc[k], 1);
    #pragma unroll
    for (int k = 0; k < HH; k++) acc[k] += __shfl_xor_sync(0xffffffffu, acc[k], 2);

    // Each lane writes its own quarter (coalesced: warp covers 1KB contiguous).
    float4* outp = (float4*)(g_nagg + (size_t)row * HH + q * 8);
    float4 lo, hi;
    if (q == 0) {
        lo = make_float4(acc[0],  acc[1],  acc[2],  acc[3]);
        hi = make_float4(acc[4],  acc[5],  acc[6],  acc[7]);
    } else if (q == 1) {
        lo = make_float4(acc[8],  acc[9],  acc[10], acc[11]);
        hi = make_float4(acc[12], acc[13], acc[14], acc[15]);
    } else if (q == 2) {
        lo = make_float4(acc[16], acc[17], acc[18], acc[19]);
        hi = make_float4(acc[20], acc[21], acc[22], acc[23]);
    } else {
        lo = make_float4(acc[24], acc[25], acc[26], acc[27]);
        hi = make_float4(acc[28], acc[29], acc[30], acc[31]);
    }
    outp[0] = lo;
    outp[1] = hi;
}

// ---------------------------------------------------------------------------
// K2: self branch + shared head, one thread per row.
// 64-dim vectors staged via padded smem (stride 65 -> bank-conflict-free)
// so rolled GEMV loops never dynamically index registers.
// ---------------------------------------------------------------------------
#define K2_THREADS 64

__global__ __launch_bounds__(K2_THREADS) void k2_rest(
    const float* __restrict__ expr,        // (B,S)
    const unsigned int* __restrict__ mask, // (B,S) bool widened to 4-byte
    const float* __restrict__ sW1,         // (1,H)
    const float* __restrict__ sb1,
    const float* __restrict__ slg,
    const float* __restrict__ slb,
    const float* __restrict__ sW2,         // (H,H)
    const float* __restrict__ sb2,
    const float* __restrict__ nb2,         // (H)  -- neighbor Linear2 bias, x N
    const float* __restrict__ hW1,         // (D,D)
    const float* __restrict__ hb1,
    const float* __restrict__ hlg,
    const float* __restrict__ hlb,
    const float* __restrict__ hW2,         // (D,O)
    const float* __restrict__ hb2,
    float* __restrict__ out)               // (B,S,O)
{
    __shared__ float s_sW1[HH], s_sb1[HH], s_slg[HH], s_slb[HH];
    __shared__ float s_sW2[HH * HH];
    __shared__ float s_sb2[HH], s_nb2[HH];
    __shared__ float s_hW1[DD * DD];
    __shared__ float s_hb1[DD], s_hlg[DD], s_hlb[DD];
    __shared__ float s_hW2[DD * OO];
    __shared__ float s_hb2[OO];
    __shared__ float s_x[K2_THREADS * 65];   // padded per-thread 64-vector

    const int tid = threadIdx.x;
    for (int i = tid; i < HH; i += K2_THREADS) {
        s_sW1[i] = sW1[i]; s_sb1[i] = sb1[i];
        s_slg[i] = slg[i]; s_slb[i] = slb[i];
        s_sb2[i] = sb2[i]; s_nb2[i] = nb2[i];
    }
    for (int i = tid; i < HH * HH; i += K2_THREADS) s_sW2[i] = sW2[i];
    for (int i = tid; i < DD * DD; i += K2_THREADS) s_hW1[i] = hW1[i];
    for (int i = tid; i < DD; i += K2_THREADS) {
        s_hb1[i] = hb1[i]; s_hlg[i] = hlg[i]; s_hlb[i] = hlb[i];
    }
    for (int i = tid; i < DD * OO; i += K2_THREADS) s_hW2[i] = hW2[i];
    for (int i = tid; i < OO; i += K2_THREADS) s_hb2[i] = hb2[i];
    __syncthreads();

    const int row = blockIdx.x * K2_THREADS + tid;
    float* xr = &s_x[tid * 65];

    // ---- self branch: Linear(1,H) -> LN -> ReLU ----
    const float ex = expr[row];
    float h[HH];
    float sum = 0.0f;
    #pragma unroll
    for (int j = 0; j < HH; j++) {
        h[j] = fmaf(ex, s_sW1[j], s_sb1[j]);
        sum += h[j];
    }
    const float m1 = sum * (1.0f / HH);
    float var1 = 0.0f;
    #pragma unroll
    for (int j = 0; j < HH; j++) {
        float d = h[j] - m1;
        var1 = fmaf(d, d, var1);
    }
    const float r1 = rsqrtf(var1 * (1.0f / HH) + LN_EPS);
    #pragma unroll
    for (int j = 0; j < HH; j++)
        xr[j] = fmaxf(fmaf((h[j] - m1) * r1, s_slg[j], s_slb[j]), 0.0f);

    // ---- e = relu(...) @ sW2 + sb2 ----
    float e[HH];
    #pragma unroll
    for (int k = 0; k < HH; k++) e[k] = s_sb2[k];
    #pragma unroll 1
    for (int j = 0; j < HH; j++) {
        const float hv = xr[j];
        #pragma unroll
        for (int k = 0; k < HH; k++)
            e[k] = fmaf(hv, s_sW2[j * HH + k], e[k]);
    }

    // ---- x = concat(e, nagg + N*nb2) into smem ----
    #pragma unroll
    for (int k = 0; k < HH; k++) xr[k] = e[k];
    const float4* nag4 = (const float4*)(g_nagg + (size_t)row * HH);
    #pragma unroll
    for (int k4 = 0; k4 < 8; k4++) {
        float4 v = nag4[k4];
        xr[HH + k4*4 + 0] = v.x + (float)NN * s_nb2[k4*4 + 0];
        xr[HH + k4*4 + 1] = v.y + (float)NN * s_nb2[k4*4 + 1];
        xr[HH + k4*4 + 2] = v.z + (float)NN * s_nb2[k4*4 + 2];
        xr[HH + k4*4 + 3] = v.w + (float)NN * s_nb2[k4*4 + 3];
    }

    // ---- y = x @ hW1 + hb1 ----
    float y[DD];
    #pragma unroll
    for (int mm = 0; mm < DD; mm++) y[mm] = s_hb1[mm];
    #pragma unroll 1
    for (int j = 0; j < DD; j++) {
        const float xv = xr[j];
        #pragma unroll
        for (int mm = 0; mm < DD; mm++)
            y[mm] = fmaf(xv, s_hW1[j * DD + mm], y[mm]);
    }

    // ---- LN(D) + ReLU -> smem ----
    float s2 = 0.0f;
    #pragma unroll
    for (int mm = 0; mm < DD; mm++) s2 += y[mm];
    const float m2 = s2 * (1.0f / DD);
    float var2 = 0.0f;
    #pragma unroll
    for (int mm = 0; mm < DD; mm++) {
        float d = y[mm] - m2;
        var2 = fmaf(d, d, var2);
    }
    const float r2 = rsqrtf(var2 * (1.0f / DD) + LN_EPS);
    #pragma unroll
    for (int mm = 0; mm < DD; mm++)
        xr[mm] = fmaxf(fmaf((y[mm] - m2) * r2, s_hlg[mm], s_hlb[mm]), 0.0f);

    // ---- out = yn @ hW2 + hb2 ----
    float o[OO];
    #pragma unroll
    for (int oo = 0; oo < OO; oo++) o[oo] = s_hb2[oo];
    #pragma unroll 1
    for (int mm = 0; mm < DD; mm++) {
        const float yv = xr[mm];
        #pragma unroll
        for (int oo = 0; oo < OO; oo++)
            o[oo] = fmaf(yv, s_hW2[mm * OO + oo], o[oo]);
    }

    // ---- mask + store ----
    // mask read as 4-byte word: nonzero test is correct whether the bool was
    // widened to int32 (0/1) or float32 (0.0f/1.0f bit patterns).
    const bool msk = (mask[row] != 0u);
    if (msk) {
        #pragma unroll
        for (int oo = 0; oo < OO; oo++) o[oo] = 0.0f;
    }
    float4* op = (float4*)(out + (size_t)row * OO);
    #pragma unroll
    for (int k4 = 0; k4 < 8; k4++)
        op[k4] = make_float4(o[k4*4+0], o[k4*4+1], o[k4*4+2], o[k4*4+3]);
}

// ---------------------------------------------------------------------------
extern "C" void kernel_launch(void* const* d_in, const int* in_sizes, int n_in,
                              void* d_out, int out_size)
{
    (void)in_sizes; (void)n_in; (void)out_size;
    const float* expr          = (const float*)d_in[0];
    const float* neighbors     = (const float*)d_in[1];
    const float* edge          = (const float*)d_in[2];
    const unsigned int* mask   = (const unsigned int*)d_in[3];
    const float* nW1 = (const float*)d_in[4];
    const float* nb1 = (const float*)d_in[5];
    const float* nlg = (const float*)d_in[6];
    const float* nlb = (const float*)d_in[7];
    const float* nW2 = (const float*)d_in[8];
    const float* nb2 = (const float*)d_in[9];
    const float* sW1 = (const float*)d_in[10];
    const float* sb1 = (const float*)d_in[11];
    const float* slg = (const float*)d_in[12];
    const float* slb = (const float*)d_in[13];
    const float* sW2 = (const float*)d_in[14];
    const float* sb2 = (const float*)d_in[15];
    const float* hW1 = (const float*)d_in[16];
    const float* hb1 = (const float*)d_in[17];
    const float* hlg = (const float*)d_in[18];
    const float* hlb = (const float*)d_in[19];
    const float* hW2 = (const float*)d_in[20];
    const float* hb2 = (const float*)d_in[21];
    float* out = (float*)d_out;

    // K1: 32768 rows * 4 threads = 131072 threads
    k1_neighbors<<<(ROWS * 4) / 256, 256>>>(neighbors, edge, nW1, nb1, nlg, nlb, nW2);
    // K2: 32768 rows, 64 threads/block
    k2_rest<<<ROWS / K2_THREADS, K2_THREADS>>>(expr, mask,
                                               sW1, sb1, slg, slb, sW2, sb2, nb2,
                                               hW1, hb1, hlg, hlb, hW2, hb2, out);
}

// round 11
// speedup vs baseline: 7.9525x; 7.9525x over previous
#include <cuda_runtime.h>

// Problem constants (fixed by setup_inputs)
#define BB 8
#define SS 4096
#define NN 32
#define HH 32
#define DD 64
#define OO 32
#define ROWS (BB*SS)        // 32768
#define LN_EPS 1e-5f
#define FULLMASK 0xffffffffu

// One warp per row. Lane roles:
//   stage 1: lane = neighbor index n (computes h_n[32] in registers)
//   after butterfly: every lane holds S[j] = sum_n relu(LN(h_n))[j], all j
//   GEMV stages: lane k owns output dim k (and dims 2k,2k+1 for the 64-wide y)
__global__ __launch_bounds__(256) void fused_gnn(
    const float* __restrict__ expr,        // (B,S)
    const float* __restrict__ neighbors,   // (B,N,S)
    const float* __restrict__ edge,        // (B,S,N)
    const unsigned int* __restrict__ mask, // (B,S) bool widened to 4 bytes
    const float* __restrict__ nW1,         // (2,H)
    const float* __restrict__ nb1,
    const float* __restrict__ nlg,
    const float* __restrict__ nlb,
    const float* __restrict__ nW2,         // (H,H)
    const float* __restrict__ nb2,
    const float* __restrict__ sW1,         // (1,H)
    const float* __restrict__ sb1,
    const float* __restrict__ slg,
    const float* __restrict__ slb,
    const float* __restrict__ sW2,         // (H,H)
    const float* __restrict__ sb2,
    const float* __restrict__ hW1,         // (D,D)
    const float* __restrict__ hb1,
    const float* __restrict__ hlg,
    const float* __restrict__ hlb,
    const float* __restrict__ hW2,         // (D,O)
    const float* __restrict__ hb2,
    float* __restrict__ out)               // (B,S,O)
{
    __shared__ float s_nW1a[HH], s_nW1b[HH], s_nb1[HH], s_nlg[HH], s_nlb[HH];
    __shared__ float s_nW2[HH * HH];
    __shared__ float s_nb2[HH];
    __shared__ float s_sW1[HH], s_sb1[HH], s_slg[HH], s_slb[HH];
    __shared__ float s_sW2[HH * HH];
    __shared__ float s_sb2[HH];
    __shared__ alignas(16) float s_hW1[DD * DD];
    __shared__ float s_hb1[DD];
    __shared__ alignas(16) float s_hlg[DD];
    __shared__ alignas(16) float s_hlb[DD];
    __shared__ float s_hW2[DD * OO];
    __shared__ float s_hb2[OO];

    const int tid = threadIdx.x;
    // cooperative smem fill
    if (tid < HH) {
        s_nW1a[tid] = nW1[tid];
        s_nW1b[tid] = nW1[HH + tid];
        s_nb1[tid]  = nb1[tid];
        s_nlg[tid]  = nlg[tid];
        s_nlb[tid]  = nlb[tid];
        s_nb2[tid]  = nb2[tid];
        s_sW1[tid]  = sW1[tid];
        s_sb1[tid]  = sb1[tid];
        s_slg[tid]  = slg[tid];
        s_slb[tid]  = slb[tid];
        s_sb2[tid]  = sb2[tid];
        s_hb2[tid]  = hb2[tid];
    } else if (tid < HH + DD) {
        const int i = tid - HH;
        s_hb1[i] = hb1[i];
        s_hlg[i] = hlg[i];
        s_hlb[i] = hlb[i];
    }
    for (int i = tid; i < HH * HH; i += 256) s_nW2[i] = nW2[i];
    for (int i = tid; i < HH * HH; i += 256) s_sW2[i] = sW2[i];
    for (int i = tid; i < DD * DD; i += 256) s_hW1[i] = hW1[i];
    for (int i = tid; i < DD * OO; i += 256) s_hW2[i] = hW2[i];
    __syncthreads();

    const int wid  = tid >> 5;
    const int lane = tid & 31;
    const int row  = blockIdx.x * 8 + wid;
    const int b    = row >> 12;             // 4096 rows per batch
    const int s    = row & (SS - 1);

    // ======================= stage 1: neighbor features ====================
    // lane = neighbor n
    const float v0 = neighbors[(size_t)b * (NN * SS) + (size_t)lane * SS + s];
    const float v1 = edge[(size_t)row * NN + lane];     // coalesced across lanes

    float h[HH];
    float sum = 0.0f, sumsq = 0.0f;
    #pragma unroll
    for (int j = 0; j < HH; j++) {
        const float hj = fmaf(v0, s_nW1a[j], fmaf(v1, s_nW1b[j], s_nb1[j]));
        h[j] = hj;
        sum  += hj;
        sumsq = fmaf(hj, hj, sumsq);
    }
    const float m   = sum * (1.0f / HH);
    const float var = fmaf(-m, m, sumsq * (1.0f / HH));
    const float r   = rsqrtf(var + LN_EPS);
    #pragma unroll
    for (int j = 0; j < HH; j++)
        h[j] = fmaxf(fmaf((h[j] - m) * r, s_nlg[j], s_nlb[j]), 0.0f);

    // Butterfly all-reduce over neighbors: h[j] -> S[j] replicated in all lanes.
    #pragma unroll
    for (int ofs = 16; ofs >= 1; ofs >>= 1) {
        #pragma unroll
        for (int j = 0; j < HH; j++)
            h[j] += __shfl_xor_sync(FULLMASK, h[j], ofs);
    }

    // nagg GEMV (once per row, not per neighbor): lane k = output dim k.
    // x_{32+k} = S @ nW2[:,k] + N * nb2[k]
    float xx = 0.0f;
    #pragma unroll
    for (int j = 0; j < HH; j++)
        xx = fmaf(h[j], s_nW2[j * HH + lane], xx);
    xx = fmaf((float)NN, s_nb2[lane], xx);

    // ======================= self branch ===================================
    const float ex = expr[row];                 // uniform load per warp
    const float hs = fmaf(ex, s_sW1[lane], s_sb1[lane]);
    float ssum = hs;
    float ssq  = hs * hs;
    #pragma unroll
    for (int ofs = 16; ofs >= 1; ofs >>= 1) {
        ssum += __shfl_xor_sync(FULLMASK, ssum, ofs);
        ssq  += __shfl_xor_sync(FULLMASK, ssq,  ofs);
    }
    const float ms   = ssum * (1.0f / HH);
    const float vars = fmaf(-ms, ms, ssq * (1.0f / HH));
    const float rs   = rsqrtf(vars + LN_EPS);
    const float rn   = fmaxf(fmaf((hs - ms) * rs, s_slg[lane], s_slb[lane]), 0.0f);

    // e_k = rn @ sW2[:,k] + sb2[k]   (rn distributed one-per-lane)
    float e = s_sb2[lane];
    #pragma unroll
    for (int j = 0; j < HH; j++) {
        const float xb = __shfl_sync(FULLMASK, rn, j);
        e = fmaf(xb, s_sW2[j * HH + lane], e);
    }

    // ======================= shared head ===================================
    // x = [e_0..e_31, xx_0..xx_31]; x_j owned by lane (j & 31).
    // y (64-dim): lane k owns dims 2k, 2k+1 (so weight reads are LDS.64).
    float y0 = s_hb1[2 * lane];
    float y1 = s_hb1[2 * lane + 1];
    #pragma unroll
    for (int j = 0; j < DD; j++) {
        const float xb = (j < HH) ? __shfl_sync(FULLMASK, e,  j)
                                  : __shfl_sync(FULLMASK, xx, j - HH);
        const float2 w = *(const float2*)&s_hW1[j * DD + 2 * lane];
        y0 = fmaf(xb, w.x, y0);
        y1 = fmaf(xb, w.y, y1);
    }

    // LN over 64 dims (distributed 2 per lane)
    float s2 = y0 + y1;
    float q2 = fmaf(y0, y0, y1 * y1);
    #pragma unroll
    for (int ofs = 16; ofs >= 1; ofs >>= 1) {
        s2 += __shfl_xor_sync(FULLMASK, s2, ofs);
        q2 += __shfl_xor_sync(FULLMASK, q2, ofs);
    }
    const float m2 = s2 * (1.0f / DD);
    const float v2 = fmaf(-m2, m2, q2 * (1.0f / DD));
    const float r2 = rsqrtf(v2 + LN_EPS);
    const float2 g2 = *(const float2*)&s_hlg[2 * lane];
    const float2 lb2 = *(const float2*)&s_hlb[2 * lane];
    const float yn0 = fmaxf(fmaf((y0 - m2) * r2, g2.x, lb2.x), 0.0f);
    const float yn1 = fmaxf(fmaf((y1 - m2) * r2, g2.y, lb2.y), 0.0f);

    // out_k = yn @ hW2[:,k] + hb2[k];  yn_j owned by lane j>>1 (comp j&1)
    float o = s_hb2[lane];
    #pragma unroll
    for (int j = 0; j < DD; j++) {
        const float xb = (j & 1) ? __shfl_sync(FULLMASK, yn1, j >> 1)
                                 : __shfl_sync(FULLMASK, yn0, j >> 1);
        o = fmaf(xb, s_hW2[j * OO + lane], o);
    }

    // mask + store (mask uniform per row; warp writes 128B contiguous)
    if (mask[row] != 0u) o = 0.0f;
    out[(size_t)row * OO + lane] = o;
}

// ---------------------------------------------------------------------------
extern "C" void kernel_launch(void* const* d_in, const int* in_sizes, int n_in,
                              void* d_out, int out_size)
{
    (void)in_sizes; (void)n_in; (void)out_size;
    const float* expr          = (const float*)d_in[0];
    const float* neighbors     = (const float*)d_in[1];
    const float* edge          = (const float*)d_in[2];
    const unsigned int* mask   = (const unsigned int*)d_in[3];
    const float* nW1 = (const float*)d_in[4];
    const float* nb1 = (const float*)d_in[5];
    const float* nlg = (const float*)d_in[6];
    const float* nlb = (const float*)d_in[7];
    const float* nW2 = (const float*)d_in[8];
    const float* nb2 = (const float*)d_in[9];
    const float* sW1 = (const float*)d_in[10];
    const float* sb1 = (const float*)d_in[11];
    const float* slg = (const float*)d_in[12];
    const float* slb = (const float*)d_in[13];
    const float* sW2 = (const float*)d_in[14];
    const float* sb2 = (const float*)d_in[15];
    const float* hW1 = (const float*)d_in[16];
    const float* hb1 = (const float*)d_in[17];
    const float* hlg = (const float*)d_in[18];
    const float* hlb = (const float*)d_in[19];
    const float* hW2 = (const float*)d_in[20];
    const float* hb2 = (const float*)d_in[21];
    float* out = (float*)d_out;

    // one warp per row: 32768 warps -> 4096 blocks of 256 threads
    fused_gnn<<<ROWS / 8, 256>>>(expr, neighbors, edge, mask,
                                 nW1, nb1, nlg, nlb, nW2, nb2,
                                 sW1, sb1, slg, slb, sW2, sb2,
                                 hW1, hb1, hlg, hlb, hW2, hb2, out);
}

// round 12
// speedup vs baseline: 10.9694x; 1.3794x over previous
#include <cuda_runtime.h>

#define BB 8
#define SS 4096
#define NN 32
#define HH 32
#define DD 64
#define OO 32
#define ROWS (BB*SS)        // 32768
#define LN_EPS 1e-5f
#define FULLMASK 0xffffffffu

// Block = 256 threads = 8 warps; each warp handles 2 consecutive rows.
// Block covers 16 consecutive rows (same batch b since 16 | 4096).
__global__ __launch_bounds__(256, 2) void fused_gnn(
    const float* __restrict__ expr,        // (B,S)
    const float* __restrict__ neighbors,   // (B,N,S)
    const float* __restrict__ edge,        // (B,S,N)
    const unsigned int* __restrict__ mask, // (B,S) bool widened to 4 bytes
    const float* __restrict__ nW1,         // (2,H)
    const float* __restrict__ nb1,
    const float* __restrict__ nlg,
    const float* __restrict__ nlb,
    const float* __restrict__ nW2,         // (H,H)
    const float* __restrict__ nb2,
    const float* __restrict__ sW1,         // (1,H)
    const float* __restrict__ sb1,
    const float* __restrict__ slg,
    const float* __restrict__ slb,
    const float* __restrict__ sW2,         // (H,H)
    const float* __restrict__ sb2,
    const float* __restrict__ hW1,         // (D,D)
    const float* __restrict__ hb1,
    const float* __restrict__ hlg,
    const float* __restrict__ hlb,
    const float* __restrict__ hW2,         // (D,O)
    const float* __restrict__ hb2,
    float* __restrict__ out)               // (B,S,O)
{
    // ---- shared memory ----
    __shared__ float4 s_nP[HH];            // {nW1a, nW1b, nb1, pad}
    __shared__ float2 s_nGL[HH];           // {nlg, nlb}
    __shared__ float  s_nb2[HH];
    __shared__ float4 s_sP[HH];            // {sW1, sb1, slg, slb}
    __shared__ float  s_sb2[HH];
    __shared__ float  s_selfStats[5];      // {mw, mb, c2, c1, c0}
    __shared__ float  s_nW2[HH * HH];
    __shared__ float  s_sW2[HH * HH];
    __shared__ alignas(16) float s_hW1[DD * DD];
    __shared__ float2 s_hb1[HH];           // hb1 as float2 per lane (dims 2k,2k+1)
    __shared__ float2 s_hGL0[HH];          // {hlg[2k],   hlb[2k]}
    __shared__ float2 s_hGL1[HH];          // {hlg[2k+1], hlb[2k+1]}
    __shared__ float  s_hW2[DD * OO];
    __shared__ float  s_hb2[OO];
    __shared__ float  s_nbr[NN * 18];      // staged neighbor tile (pad 18)

    const int tid  = threadIdx.x;
    const int wid  = tid >> 5;
    const int lane = tid & 31;

    // ---- cooperative init ----
    if (tid < HH) {
        s_nP[tid]  = make_float4(nW1[tid], nW1[HH + tid], nb1[tid], 0.0f);
        s_nGL[tid] = make_float2(nlg[tid], nlb[tid]);
        s_nb2[tid] = nb2[tid];
        s_sP[tid]  = make_float4(sW1[tid], sb1[tid], slg[tid], slb[tid]);
        s_sb2[tid] = sb2[tid];
        s_hb2[tid] = hb2[tid];
        s_hb1[tid]  = make_float2(hb1[2*tid],  hb1[2*tid+1]);
        s_hGL0[tid] = make_float2(hlg[2*tid],  hlb[2*tid]);
        s_hGL1[tid] = make_float2(hlg[2*tid+1], hlb[2*tid+1]);
    }
    for (int i = tid; i < HH * HH; i += 256) s_nW2[i] = nW2[i];
    for (int i = tid; i < HH * HH; i += 256) s_sW2[i] = sW2[i];
    for (int i = tid; i < DD * DD; i += 256) s_hW1[i] = hW1[i];
    for (int i = tid; i < DD * OO; i += 256) s_hW2[i] = hW2[i];

    // self-branch LN statistics (algebraic): var(ex) = c2*ex^2 + c1*ex + c0
    if (wid == 0) {
        const float w  = sW1[lane];
        const float bb = sb1[lane];
        float sw = w, sb_ = bb, sww = w * w, swb = w * bb, sbb = bb * bb;
        #pragma unroll
        for (int ofs = 16; ofs >= 1; ofs >>= 1) {
            sw  += __shfl_xor_sync(FULLMASK, sw,  ofs);
            sb_ += __shfl_xor_sync(FULLMASK, sb_, ofs);
            sww += __shfl_xor_sync(FULLMASK, sww, ofs);
            swb += __shfl_xor_sync(FULLMASK, swb, ofs);
            sbb += __shfl_xor_sync(FULLMASK, sbb, ofs);
        }
        if (lane == 0) {
            const float mw = sw * (1.0f / HH), mb = sb_ * (1.0f / HH);
            s_selfStats[0] = mw;
            s_selfStats[1] = mb;
            s_selfStats[2] = fmaf(-mw, mw, sww * (1.0f / HH));            // c2
            s_selfStats[3] = 2.0f * fmaf(-mw, mb, swb * (1.0f / HH));     // c1
            s_selfStats[4] = fmaf(-mb, mb, sbb * (1.0f / HH));            // c0
        }
    }

    // stage neighbor tile: rows [r0, r0+16) need neighbors[b][n][s0..s0+15]
    const int r0 = blockIdx.x * 16;
    const int b  = r0 >> 12;
    const int s0 = r0 & (SS - 1);
    {
        const int n  = tid >> 3;              // 0..31
        const int sl = (tid & 7) * 2;         // 0,2,..,14
        const float2 v = *(const float2*)(neighbors + (size_t)b * (NN * SS)
                                          + (size_t)n * SS + s0 + sl);
        *(float2*)&s_nbr[n * 18 + sl] = v;
    }
    __syncthreads();

    const int rowA = r0 + wid * 2;
    const int rowB = rowA + 1;
    const int slA  = wid * 2;

    // ================= stage 1: neighbor features (both rows) ==============
    const float v0A = s_nbr[lane * 18 + slA];
    const float v0B = s_nbr[lane * 18 + slA + 1];
    const float v1A = edge[(size_t)rowA * NN + lane];
    const float v1B = edge[(size_t)rowB * NN + lane];

    float hA[HH], hB[HH];
    float sumA = 0.f, sqA = 0.f, sumB = 0.f, sqB = 0.f;
    #pragma unroll
    for (int j = 0; j < HH; j++) {
        const float4 p = s_nP[j];
        const float a = fmaf(v0A, p.x, fmaf(v1A, p.y, p.z));
        const float c = fmaf(v0B, p.x, fmaf(v1B, p.y, p.z));
        hA[j] = a; sumA += a; sqA = fmaf(a, a, sqA);
        hB[j] = c; sumB += c; sqB = fmaf(c, c, sqB);
    }
    const float mA = sumA * (1.0f / HH);
    const float rA = rsqrtf(fmaf(-mA, mA, sqA * (1.0f / HH)) + LN_EPS);
    const float mB = sumB * (1.0f / HH);
    const float rB = rsqrtf(fmaf(-mB, mB, sqB * (1.0f / HH)) + LN_EPS);
    #pragma unroll
    for (int j = 0; j < HH; j++) {
        const float2 gl = s_nGL[j];
        hA[j] = fmaxf(fmaf((hA[j] - mA) * rA, gl.x, gl.y), 0.0f);
        hB[j] = fmaxf(fmaf((hB[j] - mB) * rB, gl.x, gl.y), 0.0f);
    }

    // ---- recursive-halving reduce-scatter: lane k ends owning dim k ------
    float a16[16], b16[16];
    {
        const int bit = (lane >> 4) & 1;
        #pragma unroll
        for (int i = 0; i < 16; i++) {
            const float sA = bit ? hA[i] : hA[i + 16];
            const float kA = bit ? hA[i + 16] : hA[i];
            a16[i] = kA + __shfl_xor_sync(FULLMASK, sA, 16);
            const float sB = bit ? hB[i] : hB[i + 16];
            const float kB = bit ? hB[i + 16] : hB[i];
            b16[i] = kB + __shfl_xor_sync(FULLMASK, sB, 16);
        }
    }
    float a8[8], b8[8];
    {
        const int bit = (lane >> 3) & 1;
        #pragma unroll
        for (int i = 0; i < 8; i++) {
            const float sA = bit ? a16[i] : a16[i + 8];
            const float kA = bit ? a16[i + 8] : a16[i];
            a8[i] = kA + __shfl_xor_sync(FULLMASK, sA, 8);
            const float sB = bit ? b16[i] : b16[i + 8];
            const float kB = bit ? b16[i + 8] : b16[i];
            b8[i] = kB + __shfl_xor_sync(FULLMASK, sB, 8);
        }
    }
    float a4[4], b4[4];
    {
        const int bit = (lane >> 2) & 1;
        #pragma unroll
        for (int i = 0; i < 4; i++) {
            const float sA = bit ? a8[i] : a8[i + 4];
            const float kA = bit ? a8[i + 4] : a8[i];
            a4[i] = kA + __shfl_xor_sync(FULLMASK, sA, 4);
            const float sB = bit ? b8[i] : b8[i + 4];
            const float kB = bit ? b8[i + 4] : b8[i];
            b4[i] = kB + __shfl_xor_sync(FULLMASK, sB, 4);
        }
    }
    float a2[2], b2v[2];
    {
        const int bit = (lane >> 1) & 1;
        #pragma unroll
        for (int i = 0; i < 2; i++) {
            const float sA = bit ? a4[i] : a4[i + 2];
            const float kA = bit ? a4[i + 2] : a4[i];
            a2[i] = kA + __shfl_xor_sync(FULLMASK, sA, 2);
            const float sB = bit ? b4[i] : b4[i + 2];
            const float kB = bit ? b4[i + 2] : b4[i];
            b2v[i] = kB + __shfl_xor_sync(FULLMASK, sB, 2);
        }
    }
    float SA, SB;
    {
        const int bit = lane & 1;
        const float sA = bit ? a2[0] : a2[1];
        const float kA = bit ? a2[1] : a2[0];
        SA = kA + __shfl_xor_sync(FULLMASK, sA, 1);
        const float sB = bit ? b2v[0] : b2v[1];
        const float kB = bit ? b2v[1] : b2v[0];
        SB = kB + __shfl_xor_sync(FULLMASK, sB, 1);
    }

    // ---- nagg GEMV (batched): xx_k = S @ nW2[:,k] + N*nb2[k] -------------
    float xxA = 0.f, xxB = 0.f;
    #pragma unroll
    for (int j = 0; j < HH; j++) {
        const float w = s_nW2[j * HH + lane];
        xxA = fmaf(__shfl_sync(FULLMASK, SA, j), w, xxA);
        xxB = fmaf(__shfl_sync(FULLMASK, SB, j), w, xxB);
    }
    {
        const float nb2v = s_nb2[lane];
        xxA = fmaf((float)NN, nb2v, xxA);
        xxB = fmaf((float)NN, nb2v, xxB);
    }

    // ================= self branch (both rows) =============================
    const float exA = expr[rowA];
    const float exB = expr[rowB];
    const float4 sp = s_sP[lane];
    const float mw = s_selfStats[0], mbb = s_selfStats[1];
    const float c2 = s_selfStats[2], c1 = s_selfStats[3], c0 = s_selfStats[4];

    const float msA = fmaf(exA, mw, mbb);
    const float msB = fmaf(exB, mw, mbb);
    const float rsA = rsqrtf(fmaf(exA, fmaf(exA, c2, c1), c0) + LN_EPS);
    const float rsB = rsqrtf(fmaf(exB, fmaf(exB, c2, c1), c0) + LN_EPS);
    const float hsA = fmaf(exA, sp.x, sp.y);
    const float hsB = fmaf(exB, sp.x, sp.y);
    const float rnA = fmaxf(fmaf((hsA - msA) * rsA, sp.z, sp.w), 0.0f);
    const float rnB = fmaxf(fmaf((hsB - msB) * rsB, sp.z, sp.w), 0.0f);

    // e_k = rn @ sW2[:,k] + sb2[k]
    const float sb2v = s_sb2[lane];
    float eA = sb2v, eB = sb2v;
    #pragma unroll
    for (int j = 0; j < HH; j++) {
        const float w = s_sW2[j * HH + lane];
        eA = fmaf(__shfl_sync(FULLMASK, rnA, j), w, eA);
        eB = fmaf(__shfl_sync(FULLMASK, rnB, j), w, eB);
    }

    // ================= shared head =========================================
    // x = [e_0..e_31, xx_0..xx_31]; lane owns y dims 2k, 2k+1.
    const float2 hb = s_hb1[lane];
    float y0A = hb.x, y1A = hb.y, y0B = hb.x, y1B = hb.y;
    #pragma unroll
    for (int j = 0; j < DD; j++) {
        const float xbA = (j < HH) ? __shfl_sync(FULLMASK, eA, j)
                                   : __shfl_sync(FULLMASK, xxA, j - HH);
        const float xbB = (j < HH) ? __shfl_sync(FULLMASK, eB, j)
                                   : __shfl_sync(FULLMASK, xxB, j - HH);
        const float2 w = *(const float2*)&s_hW1[j * DD + 2 * lane];
        y0A = fmaf(xbA, w.x, y0A); y1A = fmaf(xbA, w.y, y1A);
        y0B = fmaf(xbB, w.x, y0B); y1B = fmaf(xbB, w.y, y1B);
    }

    // LN over 64 dims (2 per lane), both rows
    float s2A = y0A + y1A, q2A = fmaf(y0A, y0A, y1A * y1A);
    float s2B = y0B + y1B, q2B = fmaf(y0B, y0B, y1B * y1B);
    #pragma unroll
    for (int ofs = 16; ofs >= 1; ofs >>= 1) {
        s2A += __shfl_xor_sync(FULLMASK, s2A, ofs);
        q2A += __shfl_xor_sync(FULLMASK, q2A, ofs);
        s2B += __shfl_xor_sync(FULLMASK, s2B, ofs);
        q2B += __shfl_xor_sync(FULLMASK, q2B, ofs);
    }
    const float m2A = s2A * (1.0f / DD);
    const float r2A = rsqrtf(fmaf(-m2A, m2A, q2A * (1.0f / DD)) + LN_EPS);
    const float m2B = s2B * (1.0f / DD);
    const float r2B = rsqrtf(fmaf(-m2B, m2B, q2B * (1.0f / DD)) + LN_EPS);
    const float2 g0 = s_hGL0[lane];
    const float2 g1 = s_hGL1[lane];
    const float yn0A = fmaxf(fmaf((y0A - m2A) * r2A, g0.x, g0.y), 0.0f);
    const float yn1A = fmaxf(fmaf((y1A - m2A) * r2A, g1.x, g1.y), 0.0f);
    const float yn0B = fmaxf(fmaf((y0B - m2B) * r2B, g0.x, g0.y), 0.0f);
    const float yn1B = fmaxf(fmaf((y1B - m2B) * r2B, g1.x, g1.y), 0.0f);

    // out_k = yn @ hW2[:,k] + hb2[k]
    const float hb2v = s_hb2[lane];
    float oA = hb2v, oB = hb2v;
    #pragma unroll
    for (int j = 0; j < DD; j++) {
        const float ybA = (j & 1) ? __shfl_sync(FULLMASK, yn1A, j >> 1)
                                  : __shfl_sync(FULLMASK, yn0A, j >> 1);
        const float ybB = (j & 1) ? __shfl_sync(FULLMASK, yn1B, j >> 1)
                                  : __shfl_sync(FULLMASK, yn0B, j >> 1);
        const float w = s_hW2[j * OO + lane];
        oA = fmaf(ybA, w, oA);
        oB = fmaf(ybB, w, oB);
    }

    // mask + store
    if (mask[rowA] != 0u) oA = 0.0f;
    if (mask[rowB] != 0u) oB = 0.0f;
    out[(size_t)rowA * OO + lane] = oA;
    out[(size_t)rowB * OO + lane] = oB;
}

// ---------------------------------------------------------------------------
extern "C" void kernel_launch(void* const* d_in, const int* in_sizes, int n_in,
                              void* d_out, int out_size)
{
    (void)in_sizes; (void)n_in; (void)out_size;
    const float* expr          = (const float*)d_in[0];
    const float* neighbors     = (const float*)d_in[1];
    const float* edge          = (const float*)d_in[2];
    const unsigned int* mask   = (const unsigned int*)d_in[3];
    const float* nW1 = (const float*)d_in[4];
    const float* nb1 = (const float*)d_in[5];
    const float* nlg = (const float*)d_in[6];
    const float* nlb = (const float*)d_in[7];
    const float* nW2 = (const float*)d_in[8];
    const float* nb2 = (const float*)d_in[9];
    const float* sW1 = (const float*)d_in[10];
    const float* sb1 = (const float*)d_in[11];
    const float* slg = (const float*)d_in[12];
    const float* slb = (const float*)d_in[13];
    const float* sW2 = (const float*)d_in[14];
    const float* sb2 = (const float*)d_in[15];
    const float* hW1 = (const float*)d_in[16];
    const float* hb1 = (const float*)d_in[17];
    const float* hlg = (const float*)d_in[18];
    const float* hlb = (const float*)d_in[19];
    const float* hW2 = (const float*)d_in[20];
    const float* hb2 = (const float*)d_in[21];
    float* out = (float*)d_out;

    // 16 rows per block -> 2048 blocks of 256 threads (2 rows per warp)
    fused_gnn<<<ROWS / 16, 256>>>(expr, neighbors, edge, mask,
                                  nW1, nb1, nlg, nlb, nW2, nb2,
                                  sW1, sb1, slg, slb, sW2, sb2,
                                  hW1, hb1, hlg, hlb, hW2, hb2, out);
}

// round 13
// speedup vs baseline: 14.9885x; 1.3664x over previous
#include <cuda_runtime.h>

#define BB 8
#define SS 4096
#define NN 32
#define HH 32
#define DD 64
#define OO 32
#define ROWS (BB*SS)        // 32768
#define LN_EPS 1e-5f
#define FULLMASK 0xffffffffu

// Block = 256 threads = 8 warps; each warp handles 2 consecutive rows.
// Stage 1 layout: lane = dim (LN stats computed algebraically per neighbor).
// GEMV broadcasts: packed float2 (rowA,rowB) via warp-private smem scratch.
__global__ __launch_bounds__(256, 3) void fused_gnn(
    const float* __restrict__ expr,        // (B,S)
    const float* __restrict__ neighbors,   // (B,N,S)
    const float* __restrict__ edge,        // (B,S,N)
    const unsigned int* __restrict__ mask, // (B,S) bool widened to 4 bytes
    const float* __restrict__ nW1,         // (2,H)
    const float* __restrict__ nb1,
    const float* __restrict__ nlg,
    const float* __restrict__ nlb,
    const float* __restrict__ nW2,         // (H,H)
    const float* __restrict__ nb2,
    const float* __restrict__ sW1,         // (1,H)
    const float* __restrict__ sb1,
    const float* __restrict__ slg,
    const float* __restrict__ slb,
    const float* __restrict__ sW2,         // (H,H)
    const float* __restrict__ sb2,
    const float* __restrict__ hW1,         // (D,D)
    const float* __restrict__ hb1,
    const float* __restrict__ hlg,
    const float* __restrict__ hlb,
    const float* __restrict__ hW2,         // (D,O)
    const float* __restrict__ hb2,
    float* __restrict__ out)               // (B,S,O)
{
    __shared__ float s_nW2[HH * HH];           // 4KB
    __shared__ float s_sW2[HH * HH];           // 4KB
    __shared__ alignas(16) float s_hW1[DD * DD];   // 16KB
    __shared__ float s_hW2[DD * OO];           // 8KB
    __shared__ float s_nbr[NN * 18];           // staged neighbor tile
    __shared__ float s_selfStats[5];           // {mw, mb, c2, c1, c0}
    __shared__ float s_nStats[9];              // {ma,mb,mc,Caa,Cbb,Ccc,Cab2,Cac2,Cbc2}
    __shared__ alignas(16) float s_buf[8][256]; // 1KB scratch per warp

    const int tid  = threadIdx.x;
    const int wid  = tid >> 5;
    const int lane = tid & 31;

    // ---- cooperative weight loads ----
    for (int i = tid; i < HH * HH; i += 256) s_nW2[i] = nW2[i];
    for (int i = tid; i < HH * HH; i += 256) s_sW2[i] = sW2[i];
    for (int i = tid; i < DD * DD; i += 256) s_hW1[i] = hW1[i];
    for (int i = tid; i < DD * OO; i += 256) s_hW2[i] = hW2[i];

    // ---- warp 0: self-branch LN stats (var(ex) = c2 ex^2 + c1 ex + c0) ----
    if (wid == 0) {
        const float w  = sW1[lane];
        const float bb = sb1[lane];
        float sw = w, sb_ = bb, sww = w * w, swb = w * bb, sbb = bb * bb;
        #pragma unroll
        for (int ofs = 16; ofs >= 1; ofs >>= 1) {
            sw  += __shfl_xor_sync(FULLMASK, sw,  ofs);
            sb_ += __shfl_xor_sync(FULLMASK, sb_, ofs);
            sww += __shfl_xor_sync(FULLMASK, sww, ofs);
            swb += __shfl_xor_sync(FULLMASK, swb, ofs);
            sbb += __shfl_xor_sync(FULLMASK, sbb, ofs);
        }
        if (lane == 0) {
            const float mw = sw * (1.0f / HH), mb = sb_ * (1.0f / HH);
            s_selfStats[0] = mw;
            s_selfStats[1] = mb;
            s_selfStats[2] = fmaf(-mw, mw, sww * (1.0f / HH));
            s_selfStats[3] = 2.0f * fmaf(-mw, mb, swb * (1.0f / HH));
            s_selfStats[4] = fmaf(-mb, mb, sbb * (1.0f / HH));
        }
    }
    // ---- warp 1: neighbor-branch LN stats (quadratic form in v0,v1) ----
    if (wid == 1) {
        const float a = nW1[lane], b = nW1[HH + lane], c = nb1[lane];
        float sa = a, sb_ = b, sc = c;
        float saa = a * a, sbb = b * b, scc = c * c;
        float sab = a * b, sac = a * c, sbc = b * c;
        #pragma unroll
        for (int ofs = 16; ofs >= 1; ofs >>= 1) {
            sa  += __shfl_xor_sync(FULLMASK, sa,  ofs);
            sb_ += __shfl_xor_sync(FULLMASK, sb_, ofs);
            sc  += __shfl_xor_sync(FULLMASK, sc,  ofs);
            saa += __shfl_xor_sync(FULLMASK, saa, ofs);
            sbb += __shfl_xor_sync(FULLMASK, sbb, ofs);
            scc += __shfl_xor_sync(FULLMASK, scc, ofs);
            sab += __shfl_xor_sync(FULLMASK, sab, ofs);
            sac += __shfl_xor_sync(FULLMASK, sac, ofs);
            sbc += __shfl_xor_sync(FULLMASK, sbc, ofs);
        }
        if (lane == 0) {
            const float ma = sa * (1.0f / HH), mb = sb_ * (1.0f / HH), mc = sc * (1.0f / HH);
            s_nStats[0] = ma; s_nStats[1] = mb; s_nStats[2] = mc;
            s_nStats[3] = fmaf(-ma, ma, saa * (1.0f / HH));           // Caa
            s_nStats[4] = fmaf(-mb, mb, sbb * (1.0f / HH));           // Cbb
            s_nStats[5] = fmaf(-mc, mc, scc * (1.0f / HH));           // Ccc
            s_nStats[6] = 2.0f * fmaf(-ma, mb, sab * (1.0f / HH));    // Cab2
            s_nStats[7] = 2.0f * fmaf(-ma, mc, sac * (1.0f / HH));    // Cac2
            s_nStats[8] = 2.0f * fmaf(-mb, mc, sbc * (1.0f / HH));    // Cbc2
        }
    }

    // ---- stage neighbor tile: rows [r0, r0+16) need neighbors[b][:][s0..s0+15]
    const int r0 = blockIdx.x * 16;
    const int b  = r0 >> 12;
    const int s0 = r0 & (SS - 1);
    {
        const int n  = tid >> 3;              // 0..31
        const int sl = (tid & 7) * 2;         // 0,2,..,14
        const float2 v = *(const float2*)(neighbors + (size_t)b * (NN * SS)
                                          + (size_t)n * SS + s0 + sl);
        *(float2*)&s_nbr[n * 18 + sl] = v;
    }
    __syncthreads();

    const int rowA = r0 + wid * 2;
    const int rowB = rowA + 1;
    const int slA  = wid * 2;
    float* buf = s_buf[wid];
    float4* f4A = (float4*)buf;               // [0..31]   (buf floats 0..127)
    float4* f4B = (float4*)(buf + 128);       // [0..31]   (buf floats 128..255)
    float2* scrS = (float2*)buf;              // buf 0..63
    float2* scrR = (float2*)(buf + 64);       // buf 64..127
    float2* scrX = (float2*)(buf + 128);      // buf 128..255 (64 entries)
    float2* scrY = (float2*)buf;              // buf 0..127   (64 entries)

    // ============== stage 1: per-neighbor LN stats (lane = neighbor) =======
    {
        const float v0A = s_nbr[lane * 18 + slA];
        const float v0B = s_nbr[lane * 18 + slA + 1];
        const float v1A = edge[(size_t)rowA * NN + lane];
        const float v1B = edge[(size_t)rowB * NN + lane];
        const float ma = s_nStats[0], mb_ = s_nStats[1], mc = s_nStats[2];
        const float Caa = s_nStats[3], Cbb = s_nStats[4], Ccc = s_nStats[5];
        const float Cab2 = s_nStats[6], Cac2 = s_nStats[7], Cbc2 = s_nStats[8];

        const float mA = fmaf(v0A, ma, fmaf(v1A, mb_, mc));
        const float vA = fmaf(v0A, fmaf(Caa, v0A, fmaf(Cab2, v1A, Cac2)),
                              fmaf(v1A, fmaf(Cbb, v1A, Cbc2), Ccc));
        const float rA = rsqrtf(vA + LN_EPS);
        const float mB = fmaf(v0B, ma, fmaf(v1B, mb_, mc));
        const float vB = fmaf(v0B, fmaf(Caa, v0B, fmaf(Cab2, v1B, Cac2)),
                              fmaf(v1B, fmaf(Cbb, v1B, Cbc2), Ccc));
        const float rB = rsqrtf(vB + LN_EPS);

        f4A[lane] = make_float4(v0A, v1A, mA, rA);
        f4B[lane] = make_float4(v0B, v1B, mB, rB);
    }
    __syncwarp();

    // ============== stage 1 accumulate: lane = dim ========================
    const float aL = nW1[lane], bL = nW1[HH + lane], cL = nb1[lane];
    const float gL = nlg[lane], lL = nlb[lane];
    float SA = 0.0f, SB = 0.0f;
    #pragma unroll
    for (int n = 0; n < NN; n++) {
        const float4 fA = f4A[n];
        const float hA = fmaf(fA.x, aL, fmaf(fA.y, bL, cL));
        SA += fmaxf(fmaf((hA - fA.z) * fA.w, gL, lL), 0.0f);
        const float4 fB = f4B[n];
        const float hB = fmaf(fB.x, aL, fmaf(fB.y, bL, cL));
        SB += fmaxf(fmaf((hB - fB.z) * fB.w, gL, lL), 0.0f);
    }
    __syncwarp();   // phase-1 reads done before scratch reuse

    // ============== self branch (lane = dim) ==============================
    const float exA = expr[rowA];
    const float exB = expr[rowB];
    float rnA, rnB;
    {
        const float spw = sW1[lane], spb = sb1[lane];
        const float spg = slg[lane], spl = slb[lane];
        const float mw = s_selfStats[0], mbb = s_selfStats[1];
        const float c2 = s_selfStats[2], c1 = s_selfStats[3], c0 = s_selfStats[4];
        const float rsA = rsqrtf(fmaf(exA, fmaf(exA, c2, c1), c0) + LN_EPS);
        const float rsB = rsqrtf(fmaf(exB, fmaf(exB, c2, c1), c0) + LN_EPS);
        rnA = fmaxf(fmaf((fmaf(exA, spw, spb) - fmaf(exA, mw, mbb)) * rsA, spg, spl), 0.0f);
        rnB = fmaxf(fmaf((fmaf(exB, spw, spb) - fmaf(exB, mw, mbb)) * rsB, spg, spl), 0.0f);
    }

    scrS[lane] = make_float2(SA, SB);
    scrR[lane] = make_float2(rnA, rnB);
    __syncwarp();

    // nagg GEMV: xx_k = S @ nW2[:,k] + N*nb2[k]
    float xxA, xxB;
    {
        const float base = (float)NN * nb2[lane];
        xxA = base; xxB = base;
    }
    #pragma unroll
    for (int j = 0; j < HH; j++) {
        const float2 sv = scrS[j];
        const float w = s_nW2[j * HH + lane];
        xxA = fmaf(sv.x, w, xxA);
        xxB = fmaf(sv.y, w, xxB);
    }
    // self GEMV: e_k = rn @ sW2[:,k] + sb2[k]
    float eA, eB;
    {
        const float base = sb2[lane];
        eA = base; eB = base;
    }
    #pragma unroll
    for (int j = 0; j < HH; j++) {
        const float2 rv = scrR[j];
        const float w = s_sW2[j * HH + lane];
        eA = fmaf(rv.x, w, eA);
        eB = fmaf(rv.y, w, eB);
    }

    // ============== shared head ===========================================
    scrX[lane]      = make_float2(eA, eB);
    scrX[HH + lane] = make_float2(xxA, xxB);
    __syncwarp();

    const float2 hbv = *(const float2*)&hb1[2 * lane];
    float y0A = hbv.x, y1A = hbv.y, y0B = hbv.x, y1B = hbv.y;
    #pragma unroll
    for (int j = 0; j < DD; j++) {
        const float2 xv = scrX[j];
        const float2 w = *(const float2*)&s_hW1[j * DD + 2 * lane];
        y0A = fmaf(xv.x, w.x, y0A); y1A = fmaf(xv.x, w.y, y1A);
        y0B = fmaf(xv.y, w.x, y0B); y1B = fmaf(xv.y, w.y, y1B);
    }

    // LN over 64 dims (2 per lane), both rows
    float s2A = y0A + y1A, q2A = fmaf(y0A, y0A, y1A * y1A);
    float s2B = y0B + y1B, q2B = fmaf(y0B, y0B, y1B * y1B);
    #pragma unroll
    for (int ofs = 16; ofs >= 1; ofs >>= 1) {
        s2A += __shfl_xor_sync(FULLMASK, s2A, ofs);
        q2A += __shfl_xor_sync(FULLMASK, q2A, ofs);
        s2B += __shfl_xor_sync(FULLMASK, s2B, ofs);
        q2B += __shfl_xor_sync(FULLMASK, q2B, ofs);
    }
    const float m2A = s2A * (1.0f / DD);
    const float r2A = rsqrtf(fmaf(-m2A, m2A, q2A * (1.0f / DD)) + LN_EPS);
    const float m2B = s2B * (1.0f / DD);
    const float r2B = rsqrtf(fmaf(-m2B, m2B, q2B * (1.0f / DD)) + LN_EPS);
    const float2 gg = *(const float2*)&hlg[2 * lane];
    const float2 lb = *(const float2*)&hlb[2 * lane];
    const float yn0A = fmaxf(fmaf((y0A - m2A) * r2A, gg.x, lb.x), 0.0f);
    const float yn1A = fmaxf(fmaf((y1A - m2A) * r2A, gg.y, lb.y), 0.0f);
    const float yn0B = fmaxf(fmaf((y0B - m2B) * r2B, gg.x, lb.x), 0.0f);
    const float yn1B = fmaxf(fmaf((y1B - m2B) * r2B, gg.y, lb.y), 0.0f);

    // scrY overlaps scrS/scrR: safe — the shfl_syncs above force convergence,
    // so all lanes have finished the GEMV loop reads.
    scrY[2 * lane]     = make_float2(yn0A, yn0B);
    scrY[2 * lane + 1] = make_float2(yn1A, yn1B);
    __syncwarp();

    // out_k = yn @ hW2[:,k] + hb2[k]
    float oA, oB;
    {
        const float base = hb2[lane];
        oA = base; oB = base;
    }
    #pragma unroll
    for (int j = 0; j < DD; j++) {
        const float2 yv = scrY[j];
        const float w = s_hW2[j * OO + lane];
        oA = fmaf(yv.x, w, oA);
        oB = fmaf(yv.y, w, oB);
    }

    // mask + store
    if (mask[rowA] != 0u) oA = 0.0f;
    if (mask[rowB] != 0u) oB = 0.0f;
    out[(size_t)rowA * OO + lane] = oA;
    out[(size_t)rowB * OO + lane] = oB;
}

// ---------------------------------------------------------------------------
extern "C" void kernel_launch(void* const* d_in, const int* in_sizes, int n_in,
                              void* d_out, int out_size)
{
    (void)in_sizes; (void)n_in; (void)out_size;
    const float* expr          = (const float*)d_in[0];
    const float* neighbors     = (const float*)d_in[1];
    const float* edge          = (const float*)d_in[2];
    const unsigned int* mask   = (const unsigned int*)d_in[3];
    const float* nW1 = (const float*)d_in[4];
    const float* nb1 = (const float*)d_in[5];
    const float* nlg = (const float*)d_in[6];
    const float* nlb = (const float*)d_in[7];
    const float* nW2 = (const float*)d_in[8];
    const float* nb2 = (const float*)d_in[9];
    const float* sW1 = (const float*)d_in[10];
    const float* sb1 = (const float*)d_in[11];
    const float* slg = (const float*)d_in[12];
    const float* slb = (const float*)d_in[13];
    const float* sW2 = (const float*)d_in[14];
    const float* sb2 = (const float*)d_in[15];
    const float* hW1 = (const float*)d_in[16];
    const float* hb1 = (const float*)d_in[17];
    const float* hlg = (const float*)d_in[18];
    const float* hlb = (const float*)d_in[19];
    const float* hW2 = (const float*)d_in[20];
    const float* hb2 = (const float*)d_in[21];
    float* out = (float*)d_out;

    // 16 rows per block -> 2048 blocks of 256 threads (2 rows per warp)
    fused_gnn<<<ROWS / 16, 256>>>(expr, neighbors, edge, mask,
                                  nW1, nb1, nlg, nlb, nW2, nb2,
                                  sW1, sb1, slg, slb, sW2, sb2,
                                  hW1, hb1, hlg, hlb, hW2, hb2, out);
}